// round 14
// baseline (speedup 1.0000x reference)
#include <cuda_runtime.h>
#include <cstdint>

// SemiConv2d: 5x5 max-plus dilation, 'same' padding with -inf.
// input:  (16, 64, 256, 256) fp32 -> 1024 independent 256x256 images
// kernel: (5, 5) fp32
//
// Row-streaming, 5 rotating accumulator slots, 4 cols/thread (float4 I/O),
// software-prefetched double-buffered loads (R6), boundary peeling (R7),
// masked head/tail, 64-thread blocks (R11). R12's f32x2 reverted (FADD2 is
// half-rate on the fma pipe + pack MOVs on alu).
// R13 changes:
//  1) ONE-GENERATION SCHEDULE: 3 strips of 86 rows per image (i0=0/85/170,
//     1-row overlap rows written twice with identical values). Jobs =
//     1024x2x3 = 6144 warp-jobs = 3072 blocks <= 3108 resident capacity
//     (21 blocks/SM @ 48 regs) -> single generation, 98.8% slot fill,
//     no partial second wave. Work/image-half: 270 steps vs 272 before.
//  2) g_ninf statically initialized -> fill kernel launch removed.

#define IMG_H 256
#define IMG_W 256
#define NIF (-__builtin_huge_valf())

__device__ __align__(16) float g_ninf[16] = {
    NIF, NIF, NIF, NIF, NIF, NIF, NIF, NIF,
    NIF, NIF, NIF, NIF, NIF, NIF, NIF, NIF
};

__global__ void __launch_bounds__(64) dil5x5_kernel(
    const float* __restrict__ x,
    const float* __restrict__ kw,
    float* __restrict__ out)
{
    const int lane   = threadIdx.x & 31;
    const int half   = threadIdx.x >> 5;          // 0..1 -> 128-col half

    const int bj    = blockIdx.x;                 // 0..3071
    const int img   = bj / 3;                     // 0..1023
    const int strip = bj - img * 3;               // 0..2
    const int i0    = strip * 85;                 // 0, 85, 170 (86 rows each)

    const int j0 = (half << 7) + (lane << 2);     // first of 4 output cols

    float k[25];
#pragma unroll
    for (int t = 0; t < 25; ++t) k[t] = kw[t];

    const float NI = __int_as_float(0xff800000u);

    float acc[5][4];
#pragma unroll
    for (int q = 0; q < 5; ++q)
#pragma unroll
        for (int c = 0; c < 4; ++c) acc[q][c] = NI;

    const float* xim = x   + (size_t)img * (IMG_H * IMG_W);
    float*       oim = out + (size_t)img * (IMG_H * IMG_W);

    // Column-halo validity (loop-invariant). A covers cols j0-4..j0-1 (we
    // use j0-2,j0-1): invalid only when j0==0. C covers j0+4..j0+7 (we use
    // j0+4,j0+5): invalid only when j0==252. B always valid.
    const bool c0ok = (j0 != 0);
    const bool c2ok = (j0 != 252);

    // Row-halo validity: rows i0-2,i0-1 exist unless strip==0; rows
    // i0+86,i0+87 exist unless strip==2 (bottom strip, i0=170).
    const bool topok = (strip != 0);
    const bool botok = (strip != 2);

    const float4 NIV = make_float4(NI, NI, NI, NI);
    float4 Ab[2] = {NIV, NIV}, Bb[2] = {NIV, NIV}, Cb[2] = {NIV, NIV};

    const float* ninf = g_ninf;   // 16 floats of -inf (static init)

    // Load a row (base pointer at col j0-4) into buffer DSTP.
#define PREF(DSTP, RP)                                                       \
    {                                                                        \
        const float* _rp = (RP);                                             \
        if (c0ok) Ab[DSTP] = *(const float4*)(_rp);                          \
        Bb[DSTP] = *(const float4*)(_rp + 4);                                \
        if (c2ok) Cb[DSTP] = *(const float4*)(_rp + 8);                      \
    }

    // Apply buffer CUR to the rotating slots selected by compile-time MASK
    // (phase PH); optionally store the completed slot PH (finishes kernel
    // row u=4 this step).
#define MATH(PH, CUR, STOREF, OPTR, MASK)                                    \
    {                                                                        \
        float X[12] = {Ab[CUR].x, Ab[CUR].y, Ab[CUR].z, Ab[CUR].w,           \
                       Bb[CUR].x, Bb[CUR].y, Bb[CUR].z, Bb[CUR].w,           \
                       Cb[CUR].x, Cb[CUR].y, Cb[CUR].z, Cb[CUR].w};          \
        _Pragma("unroll")                                                    \
        for (int q = 0; q < 5; ++q) {                                        \
            if ((((MASK) >> q) & 1) == 0) continue;  /* compile-time */      \
            const int d = (q - (PH) + 5) % 5;   /* compile-time */           \
            const int u = 4 - d;                /* kernel row   */           \
            if (d == 4) {                                                    \
                _Pragma("unroll")                                            \
                for (int c = 0; c < 4; ++c)                                  \
                    acc[q][c] = X[c + 2] + k[u * 5 + 0];                     \
                _Pragma("unroll")                                            \
                for (int v = 1; v < 5; ++v)                                  \
                    _Pragma("unroll")                                        \
                    for (int c = 0; c < 4; ++c)                              \
                        acc[q][c] = fmaxf(acc[q][c], X[c + v + 2] + k[u * 5 + v]); \
            } else {                                                         \
                _Pragma("unroll")                                            \
                for (int v = 0; v < 5; ++v)                                  \
                    _Pragma("unroll")                                        \
                    for (int c = 0; c < 4; ++c)                              \
                        acc[q][c] = fmaxf(acc[q][c], X[c + v + 2] + k[u * 5 + v]); \
            }                                                                \
        }                                                                    \
        if (STOREF)                                                          \
            *(float4*)(OPTR) = make_float4(acc[PH][0], acc[PH][1],           \
                                           acc[PH][2], acc[PH][3]);          \
    }

    // Steps s = 0..89. Step s consumes input row r = i0+s-2 and prefetches
    // row i0+s-1; output row i0+s-4 emits at s>=4 (outputs i0..i0+85).
    // pbase -> row i0-2, col j0-4
    const float* pbase = xim + (ptrdiff_t)(i0 - 2) * IMG_W + (j0 - 4);

    // Prologue: buffer 0 <- row i0-2 (or -inf for the top strip).
    PREF(0, topok ? pbase : ninf)

    // Head, steps s=0..3 (no stores). Slot q is initialized at its d==4
    // step: s0->slot4, s1->slot0, s2->slot1, s3->slot2. Masks include only
    // already-initialized slots. Prefetch rows i0-1 (guarded), i0, i0+1,
    // i0+2 (valid for every strip).
    PREF(1, topok ? pbase + 1 * IMG_W : ninf)  MATH(0, 0, 0, oim, 0x10)
    PREF(0, pbase + 2 * IMG_W)                 MATH(1, 1, 0, oim, 0x11)
    PREF(1, pbase + 3 * IMG_W)                 MATH(2, 0, 0, oim, 0x13)
    PREF(0, pbase + 4 * IMG_W)                 MATH(3, 1, 0, oim, 0x17)

    // Steady state, steps s=4..83 (8 x 10): all slots live, unconditional
    // loads/stores, immediate offsets, pointers bumped once per 10 steps.
    // Prefetch rows i0+3..i0+82 (max 252 < 256: valid for every strip).
    const float* pb = pbase + 5 * IMG_W;             // row i0+3 (first prefetch)
    float*       ob = oim + (size_t)i0 * IMG_W + j0; // row i0 (first store)
    for (int g = 0; g < 8; ++g) {
        PREF(1, pb + 0 * IMG_W)  MATH(4, 0, 1, ob + 0 * IMG_W, 0x1F)
        PREF(0, pb + 1 * IMG_W)  MATH(0, 1, 1, ob + 1 * IMG_W, 0x1F)
        PREF(1, pb + 2 * IMG_W)  MATH(1, 0, 1, ob + 2 * IMG_W, 0x1F)
        PREF(0, pb + 3 * IMG_W)  MATH(2, 1, 1, ob + 3 * IMG_W, 0x1F)
        PREF(1, pb + 4 * IMG_W)  MATH(3, 0, 1, ob + 4 * IMG_W, 0x1F)
        PREF(0, pb + 5 * IMG_W)  MATH(4, 1, 1, ob + 5 * IMG_W, 0x1F)
        PREF(1, pb + 6 * IMG_W)  MATH(0, 0, 1, ob + 6 * IMG_W, 0x1F)
        PREF(0, pb + 7 * IMG_W)  MATH(1, 1, 1, ob + 7 * IMG_W, 0x1F)
        PREF(1, pb + 8 * IMG_W)  MATH(2, 0, 1, ob + 8 * IMG_W, 0x1F)
        PREF(0, pb + 9 * IMG_W)  MATH(3, 1, 1, ob + 9 * IMG_W, 0x1F)
        pb += 10 * IMG_W;
        ob += 10 * IMG_W;
    }
    // After loop: pb -> row i0+83 (next prefetch), ob -> output row i0+80.

    // Remainder, steps s=84..89 (phases 4,0,1,2,3,4; CUR 0,1,0,1,0,1).
    // Prefetch rows i0+83, i0+84, i0+85 (valid), i0+86, i0+87 (guarded for
    // the bottom strip), none. Masks drop slots whose next emission would
    // be at s>=90 (outputs beyond i0+85).
    PREF(1, pb + 0 * IMG_W)                    MATH(4, 0, 1, ob + 0 * IMG_W, 0x1F)
    PREF(0, pb + 1 * IMG_W)                    MATH(0, 1, 1, ob + 1 * IMG_W, 0x1F)
    PREF(1, pb + 2 * IMG_W)                    MATH(1, 0, 1, ob + 2 * IMG_W, 0x1E)
    PREF(0, botok ? pb + 3 * IMG_W : ninf)     MATH(2, 1, 1, ob + 3 * IMG_W, 0x1C)
    PREF(1, botok ? pb + 4 * IMG_W : ninf)     MATH(3, 0, 1, ob + 4 * IMG_W, 0x18)
    /* no prefetch for the final step */       MATH(4, 1, 1, ob + 5 * IMG_W, 0x10)

#undef PREF
#undef MATH
}

extern "C" void kernel_launch(void* const* d_in, const int* in_sizes, int n_in,
                              void* d_out, int out_size) {
    const float* x  = (const float*)d_in[0];  // (16,64,256,256)
    const float* kw = (const float*)d_in[1];  // (5,5)
    float* out = (float*)d_out;
    // 6144 warp-jobs = 1024 images x 3 strips (86 rows, 1-row overlap) x
    // 2 column-halves; 2 warps per 64-thread block -> 3072 blocks, all
    // co-resident in a single generation.
    dil5x5_kernel<<<3072, 64>>>(x, kw, out);
}

// round 16
// speedup vs baseline: 1.0390x; 1.0390x over previous
#include <cuda_runtime.h>
#include <cstdint>

// SemiConv2d: 5x5 max-plus dilation, 'same' padding with -inf.
// input:  (16, 64, 256, 256) fp32 -> 1024 independent 256x256 images
// kernel: (5, 5) fp32
//
// Row-streaming, 5 rotating accumulator slots, 4 cols/thread (float4 I/O),
// software-prefetched double-buffered loads (R6), boundary peeling (R7),
// masked head/tail + 64-thread blocks (R11 = best kernel time, ncu 101.8us).
// R15 change: R11 kernel EXACTLY, but g_ninf statically initialized so the
// fill_ninf pre-kernel disappears from the graph. The bench-vs-ncu gap was
// 9.4us with the fill kernel (R11) vs 1.3us without (R13): ~7-8us of pure
// launch/serialization overhead per replay, removed without touching the
// main kernel.

#define IMG_H 256
#define IMG_W 256
#define NIF (-__builtin_huge_valf())

__device__ __align__(16) float g_ninf[16] = {
    NIF, NIF, NIF, NIF, NIF, NIF, NIF, NIF,
    NIF, NIF, NIF, NIF, NIF, NIF, NIF, NIF
};

__global__ void __launch_bounds__(64) dil5x5_kernel(
    const float* __restrict__ x,
    const float* __restrict__ kw,
    float* __restrict__ out)
{
    const int lane   = threadIdx.x & 31;
    const int wlocal = threadIdx.x >> 5;
    const int w      = blockIdx.x * 2 + wlocal;   // warp-task id, 0..8191

    const int img   = w >> 3;          // 0..1023
    const int strip = (w >> 1) & 3;    // 0..3  -> 64-row strip
    const int half  = w & 1;           // 0..1  -> 128-col half

    const int i0 = strip << 6;                    // first output row of strip
    const int j0 = (half << 7) + (lane << 2);     // first of 4 output cols

    float k[25];
#pragma unroll
    for (int t = 0; t < 25; ++t) k[t] = kw[t];

    const float NI = __int_as_float(0xff800000u);

    float acc[5][4];
#pragma unroll
    for (int q = 0; q < 5; ++q)
#pragma unroll
        for (int c = 0; c < 4; ++c) acc[q][c] = NI;

    const float* xim = x   + (size_t)img * (IMG_H * IMG_W);
    float*       oim = out + (size_t)img * (IMG_H * IMG_W);

    // Column-halo validity (loop-invariant). A covers cols j0-4..j0-1 (we
    // use j0-2,j0-1): invalid only when j0==0. C covers j0+4..j0+7 (we use
    // j0+4,j0+5): invalid only when j0==252. B always valid.
    const bool c0ok = (j0 != 0);
    const bool c2ok = (j0 != 252);

    // Row-halo validity: rows i0-2,i0-1 exist unless strip==0; rows
    // i0+64,i0+65 exist unless strip==3.
    const bool topok = (strip != 0);
    const bool botok = (strip != 3);

    const float4 NIV = make_float4(NI, NI, NI, NI);
    float4 Ab[2] = {NIV, NIV}, Bb[2] = {NIV, NIV}, Cb[2] = {NIV, NIV};

    const float* ninf = g_ninf;   // 16 floats of -inf (static init)

    // Load a row (base pointer at col j0-4) into buffer DSTP.
#define PREF(DSTP, RP)                                                       \
    {                                                                        \
        const float* _rp = (RP);                                             \
        if (c0ok) Ab[DSTP] = *(const float4*)(_rp);                          \
        Bb[DSTP] = *(const float4*)(_rp + 4);                                \
        if (c2ok) Cb[DSTP] = *(const float4*)(_rp + 8);                      \
    }

    // Apply buffer CUR to the rotating slots selected by compile-time MASK
    // (phase PH); optionally store the completed slot PH (finishes kernel
    // row u=4 this step).
#define MATH(PH, CUR, STOREF, OPTR, MASK)                                    \
    {                                                                        \
        float X[12] = {Ab[CUR].x, Ab[CUR].y, Ab[CUR].z, Ab[CUR].w,           \
                       Bb[CUR].x, Bb[CUR].y, Bb[CUR].z, Bb[CUR].w,           \
                       Cb[CUR].x, Cb[CUR].y, Cb[CUR].z, Cb[CUR].w};          \
        _Pragma("unroll")                                                    \
        for (int q = 0; q < 5; ++q) {                                        \
            if ((((MASK) >> q) & 1) == 0) continue;  /* compile-time */      \
            const int d = (q - (PH) + 5) % 5;   /* compile-time */           \
            const int u = 4 - d;                /* kernel row   */           \
            if (d == 4) {                                                    \
                _Pragma("unroll")                                            \
                for (int c = 0; c < 4; ++c)                                  \
                    acc[q][c] = X[c + 2] + k[u * 5 + 0];                     \
                _Pragma("unroll")                                            \
                for (int v = 1; v < 5; ++v)                                  \
                    _Pragma("unroll")                                        \
                    for (int c = 0; c < 4; ++c)                              \
                        acc[q][c] = fmaxf(acc[q][c], X[c + v + 2] + k[u * 5 + v]); \
            } else {                                                         \
                _Pragma("unroll")                                            \
                for (int v = 0; v < 5; ++v)                                  \
                    _Pragma("unroll")                                        \
                    for (int c = 0; c < 4; ++c)                              \
                        acc[q][c] = fmaxf(acc[q][c], X[c + v + 2] + k[u * 5 + v]); \
            }                                                                \
        }                                                                    \
        if (STOREF)                                                          \
            *(float4*)(OPTR) = make_float4(acc[PH][0], acc[PH][1],           \
                                           acc[PH][2], acc[PH][3]);          \
    }

    // pbase -> row i0-2, col j0-4
    const float* pbase = xim + (ptrdiff_t)(i0 - 2) * IMG_W + (j0 - 4);

    // Prologue: buffer 0 <- row i0-2 (or -inf for the top strip).
    PREF(0, topok ? pbase : ninf)

    // Head, steps s=0..3 (consume rows i0-2..i0+1, no stores). Slot q is
    // initialized at its d==4 step: s0->slot4, s1->slot0, s2->slot1,
    // s3->slot2. Masks include only already-initialized slots.
    PREF(1, topok ? pbase + 1 * IMG_W : ninf)  MATH(0, 0, 0, oim, 0x10)
    PREF(0, pbase + 2 * IMG_W)                 MATH(1, 1, 0, oim, 0x11)
    PREF(1, pbase + 3 * IMG_W)                 MATH(2, 0, 0, oim, 0x13)
    PREF(0, pbase + 4 * IMG_W)                 MATH(3, 1, 0, oim, 0x17)

    // Steady state, steps s=4..63: all slots live, unconditional loads and
    // stores, immediate offsets, pointers bumped once per 10 steps.
    const float* pb = pbase + 5 * IMG_W;             // row i0+3 (first prefetch)
    float*       ob = oim + (size_t)i0 * IMG_W + j0; // row i0 (first store)
    for (int g = 0; g < 6; ++g) {
        PREF(1, pb + 0 * IMG_W)  MATH(4, 0, 1, ob + 0 * IMG_W, 0x1F)
        PREF(0, pb + 1 * IMG_W)  MATH(0, 1, 1, ob + 1 * IMG_W, 0x1F)
        PREF(1, pb + 2 * IMG_W)  MATH(1, 0, 1, ob + 2 * IMG_W, 0x1F)
        PREF(0, pb + 3 * IMG_W)  MATH(2, 1, 1, ob + 3 * IMG_W, 0x1F)
        PREF(1, pb + 4 * IMG_W)  MATH(3, 0, 1, ob + 4 * IMG_W, 0x1F)
        PREF(0, pb + 5 * IMG_W)  MATH(4, 1, 1, ob + 5 * IMG_W, 0x1F)
        PREF(1, pb + 6 * IMG_W)  MATH(0, 0, 1, ob + 6 * IMG_W, 0x1F)
        PREF(0, pb + 7 * IMG_W)  MATH(1, 1, 1, ob + 7 * IMG_W, 0x1F)
        PREF(1, pb + 8 * IMG_W)  MATH(2, 0, 1, ob + 8 * IMG_W, 0x1F)
        PREF(0, pb + 9 * IMG_W)  MATH(3, 1, 1, ob + 9 * IMG_W, 0x1F)
        pb += 10 * IMG_W;
        ob += 10 * IMG_W;
    }
    // After loop: pb -> row i0+63 (next prefetch), ob -> output row i0+60.

    // Tail, steps s=64..67 (phases 4,0,1,2; CUR 0,1,0,1). Emitted slots
    // need no further updates; slot3 never emits. Prefetch rows i0+63
    // (valid), i0+64, i0+65 (valid unless bottom strip), none.
    PREF(1, pb + 0 * IMG_W)                    MATH(4, 0, 1, ob + 0 * IMG_W, 0x17)
    PREF(0, botok ? pb + 1 * IMG_W : ninf)     MATH(0, 1, 1, ob + 1 * IMG_W, 0x07)
    PREF(1, botok ? pb + 2 * IMG_W : ninf)     MATH(1, 0, 1, ob + 2 * IMG_W, 0x06)
    /* no prefetch for the final step */       MATH(2, 1, 1, ob + 3 * IMG_W, 0x04)

#undef PREF
#undef MATH
}

extern "C" void kernel_launch(void* const* d_in, const int* in_sizes, int n_in,
                              void* d_out, int out_size) {
    const float* x  = (const float*)d_in[0];  // (16,64,256,256)
    const float* kw = (const float*)d_in[1];  // (5,5)
    float* out = (float*)d_out;
    // 8192 warp-tasks = 1024 images x 4 row-strips x 2 column-halves,
    // 2 warps (one strip: both halves) per 64-thread block. Single kernel:
    // no fill pre-kernel (g_ninf statically initialized).
    dil5x5_kernel<<<4096, 64>>>(x, kw, out);
}

// round 17
// speedup vs baseline: 1.0408x; 1.0018x over previous
#include <cuda_runtime.h>
#include <cstdint>

// SemiConv2d: 5x5 max-plus dilation, 'same' padding with -inf.
// input:  (16, 64, 256, 256) fp32 -> 1024 independent 256x256 images
// kernel: (5, 5) fp32
//
// Row-streaming, 5 rotating accumulator slots, 4 cols/thread (float4 I/O),
// software-prefetched double-buffered loads (R6), boundary peeling (R7),
// masked head/tail + 64-thread blocks (R11), static g_ninf (R15).
// R16 changes:
//  1) __launch_bounds__(64, 23): clamp regs 48 -> 44 so 23 blocks/SM fit
//     = 46 warps/SM (vs 42). Residency is the one variable that tracked
//     issue%% across all rounds (40w->77.5%%, 42w->75%%, 28w->68%%).
//  2) Emitting-slot-first MATH order: q = (PH+qq)%%5 so the storing slot
//     (u=4) finishes first and the STG issues ~160 slots earlier,
//     shortening the acc live-range peak (helps ptxas hit 44 regs).

#define IMG_H 256
#define IMG_W 256
#define NIF (-__builtin_huge_valf())

__device__ __align__(16) float g_ninf[16] = {
    NIF, NIF, NIF, NIF, NIF, NIF, NIF, NIF,
    NIF, NIF, NIF, NIF, NIF, NIF, NIF, NIF
};

__global__ void __launch_bounds__(64, 23) dil5x5_kernel(
    const float* __restrict__ x,
    const float* __restrict__ kw,
    float* __restrict__ out)
{
    const int lane   = threadIdx.x & 31;
    const int wlocal = threadIdx.x >> 5;
    const int w      = blockIdx.x * 2 + wlocal;   // warp-task id, 0..8191

    const int img   = w >> 3;          // 0..1023
    const int strip = (w >> 1) & 3;    // 0..3  -> 64-row strip
    const int half  = w & 1;           // 0..1  -> 128-col half

    const int i0 = strip << 6;                    // first output row of strip
    const int j0 = (half << 7) + (lane << 2);     // first of 4 output cols

    float k[25];
#pragma unroll
    for (int t = 0; t < 25; ++t) k[t] = kw[t];

    const float NI = __int_as_float(0xff800000u);

    float acc[5][4];
#pragma unroll
    for (int q = 0; q < 5; ++q)
#pragma unroll
        for (int c = 0; c < 4; ++c) acc[q][c] = NI;

    const float* xim = x   + (size_t)img * (IMG_H * IMG_W);
    float*       oim = out + (size_t)img * (IMG_H * IMG_W);

    // Column-halo validity (loop-invariant). A covers cols j0-4..j0-1 (we
    // use j0-2,j0-1): invalid only when j0==0. C covers j0+4..j0+7 (we use
    // j0+4,j0+5): invalid only when j0==252. B always valid.
    const bool c0ok = (j0 != 0);
    const bool c2ok = (j0 != 252);

    // Row-halo validity: rows i0-2,i0-1 exist unless strip==0; rows
    // i0+64,i0+65 exist unless strip==3.
    const bool topok = (strip != 0);
    const bool botok = (strip != 3);

    const float4 NIV = make_float4(NI, NI, NI, NI);
    float4 Ab[2] = {NIV, NIV}, Bb[2] = {NIV, NIV}, Cb[2] = {NIV, NIV};

    const float* ninf = g_ninf;   // 16 floats of -inf (static init)

    // Load a row (base pointer at col j0-4) into buffer DSTP.
#define PREF(DSTP, RP)                                                       \
    {                                                                        \
        const float* _rp = (RP);                                             \
        if (c0ok) Ab[DSTP] = *(const float4*)(_rp);                          \
        Bb[DSTP] = *(const float4*)(_rp + 4);                                \
        if (c2ok) Cb[DSTP] = *(const float4*)(_rp + 8);                      \
    }

    // Apply buffer CUR to the rotating slots selected by compile-time MASK
    // (phase PH). Slots are processed emitting-slot-first: qq=0 -> q=PH
    // (d=0, kernel row u=4, emits if STOREF) with its store issued
    // immediately; then qq=1..4 -> q=(PH+qq)%5, d=qq, u=4-qq (qq==4 is the
    // freshly-initialized slot).
#define MATH(PH, CUR, STOREF, OPTR, MASK)                                    \
    {                                                                        \
        float X[12] = {Ab[CUR].x, Ab[CUR].y, Ab[CUR].z, Ab[CUR].w,           \
                       Bb[CUR].x, Bb[CUR].y, Bb[CUR].z, Bb[CUR].w,           \
                       Cb[CUR].x, Cb[CUR].y, Cb[CUR].z, Cb[CUR].w};          \
        /* emitting slot first: q = PH, u = 4 */                             \
        if ((((MASK) >> (PH)) & 1) != 0) {                                   \
            _Pragma("unroll")                                                \
            for (int v = 0; v < 5; ++v)                                      \
                _Pragma("unroll")                                            \
                for (int c = 0; c < 4; ++c)                                  \
                    acc[PH][c] = fmaxf(acc[PH][c], X[c + v + 2] + k[4 * 5 + v]); \
        }                                                                    \
        if (STOREF)                                                          \
            *(float4*)(OPTR) = make_float4(acc[PH][0], acc[PH][1],           \
                                           acc[PH][2], acc[PH][3]);          \
        _Pragma("unroll")                                                    \
        for (int qq = 1; qq < 5; ++qq) {                                     \
            const int q = ((PH) + qq) % 5;      /* compile-time */           \
            if ((((MASK) >> q) & 1) == 0) continue;                          \
            const int d = qq;                                                \
            const int u = 4 - d;                /* kernel row   */           \
            if (d == 4) {                                                    \
                _Pragma("unroll")                                            \
                for (int c = 0; c < 4; ++c)                                  \
                    acc[q][c] = X[c + 2] + k[u * 5 + 0];                     \
                _Pragma("unroll")                                            \
                for (int v = 1; v < 5; ++v)                                  \
                    _Pragma("unroll")                                        \
                    for (int c = 0; c < 4; ++c)                              \
                        acc[q][c] = fmaxf(acc[q][c], X[c + v + 2] + k[u * 5 + v]); \
            } else {                                                         \
                _Pragma("unroll")                                            \
                for (int v = 0; v < 5; ++v)                                  \
                    _Pragma("unroll")                                        \
                    for (int c = 0; c < 4; ++c)                              \
                        acc[q][c] = fmaxf(acc[q][c], X[c + v + 2] + k[u * 5 + v]); \
            }                                                                \
        }                                                                    \
    }

    // pbase -> row i0-2, col j0-4
    const float* pbase = xim + (ptrdiff_t)(i0 - 2) * IMG_W + (j0 - 4);

    // Prologue: buffer 0 <- row i0-2 (or -inf for the top strip).
    PREF(0, topok ? pbase : ninf)

    // Head, steps s=0..3 (consume rows i0-2..i0+1, no stores). Slot q is
    // initialized at its d==4 step: s0->slot4, s1->slot0, s2->slot1,
    // s3->slot2. Masks include only already-initialized slots.
    PREF(1, topok ? pbase + 1 * IMG_W : ninf)  MATH(0, 0, 0, oim, 0x10)
    PREF(0, pbase + 2 * IMG_W)                 MATH(1, 1, 0, oim, 0x11)
    PREF(1, pbase + 3 * IMG_W)                 MATH(2, 0, 0, oim, 0x13)
    PREF(0, pbase + 4 * IMG_W)                 MATH(3, 1, 0, oim, 0x17)

    // Steady state, steps s=4..63: all slots live, unconditional loads and
    // stores, immediate offsets, pointers bumped once per 10 steps.
    const float* pb = pbase + 5 * IMG_W;             // row i0+3 (first prefetch)
    float*       ob = oim + (size_t)i0 * IMG_W + j0; // row i0 (first store)
    for (int g = 0; g < 6; ++g) {
        PREF(1, pb + 0 * IMG_W)  MATH(4, 0, 1, ob + 0 * IMG_W, 0x1F)
        PREF(0, pb + 1 * IMG_W)  MATH(0, 1, 1, ob + 1 * IMG_W, 0x1F)
        PREF(1, pb + 2 * IMG_W)  MATH(1, 0, 1, ob + 2 * IMG_W, 0x1F)
        PREF(0, pb + 3 * IMG_W)  MATH(2, 1, 1, ob + 3 * IMG_W, 0x1F)
        PREF(1, pb + 4 * IMG_W)  MATH(3, 0, 1, ob + 4 * IMG_W, 0x1F)
        PREF(0, pb + 5 * IMG_W)  MATH(4, 1, 1, ob + 5 * IMG_W, 0x1F)
        PREF(1, pb + 6 * IMG_W)  MATH(0, 0, 1, ob + 6 * IMG_W, 0x1F)
        PREF(0, pb + 7 * IMG_W)  MATH(1, 1, 1, ob + 7 * IMG_W, 0x1F)
        PREF(1, pb + 8 * IMG_W)  MATH(2, 0, 1, ob + 8 * IMG_W, 0x1F)
        PREF(0, pb + 9 * IMG_W)  MATH(3, 1, 1, ob + 9 * IMG_W, 0x1F)
        pb += 10 * IMG_W;
        ob += 10 * IMG_W;
    }
    // After loop: pb -> row i0+63 (next prefetch), ob -> output row i0+60.

    // Tail, steps s=64..67 (phases 4,0,1,2; CUR 0,1,0,1). Emitted slots
    // need no further updates; slot3 never emits. Prefetch rows i0+63
    // (valid), i0+64, i0+65 (valid unless bottom strip), none.
    PREF(1, pb + 0 * IMG_W)                    MATH(4, 0, 1, ob + 0 * IMG_W, 0x17)
    PREF(0, botok ? pb + 1 * IMG_W : ninf)     MATH(0, 1, 1, ob + 1 * IMG_W, 0x07)
    PREF(1, botok ? pb + 2 * IMG_W : ninf)     MATH(1, 0, 1, ob + 2 * IMG_W, 0x06)
    /* no prefetch for the final step */       MATH(2, 1, 1, ob + 3 * IMG_W, 0x04)

#undef PREF
#undef MATH
}

extern "C" void kernel_launch(void* const* d_in, const int* in_sizes, int n_in,
                              void* d_out, int out_size) {
    const float* x  = (const float*)d_in[0];  // (16,64,256,256)
    const float* kw = (const float*)d_in[1];  // (5,5)
    float* out = (float*)d_out;
    // 8192 warp-tasks = 1024 images x 4 row-strips x 2 column-halves,
    // 2 warps (one strip: both halves) per 64-thread block. Single kernel.
    dil5x5_kernel<<<4096, 64>>>(x, kw, out);
}